// round 15
// baseline (speedup 1.0000x reference)
#include <cuda_runtime.h>
#include <cstdint>

// x [B=2, T=256, N=1024, C=256] fp32.  GEMM per batch: Y[s,j] = sum_t W[s,t] X[t,j],
// fused with sigmoid gate + channel-sliced temporal shift epilogue.
// Legacy mma.sync tf32 path (tcgen05 not available at compute_103 PTX level).

constexpr int T_DIM  = 256;     // time = M = K
constexpr int NCOLS  = 262144;  // N*C per batch
constexpr int BATCH  = 2;
constexpr int CTILE  = 128;     // columns per CTA
constexpr int NKC    = 8;       // K chunks of 32
constexpr int XSTR   = 136;     // X smem row stride (floats) -> conflict-free B frags
constexpr int NTHREADS = 512;   // 16 warps: 8 (M) x 2 (N)

// Fragment-packed W: [kc(8)][ks(4)][wm(8)][mt(2)][lane(32)] float4 = 65536 floats
__device__ float Wpk_g[T_DIM * T_DIM];

// SMEM (floats): Xs[256][136] + Wfrag[2][8192] + bias[256]
constexpr int WFRAG_CHUNK = 8192;       // floats per K-chunk of packed W
constexpr int SMEM_FLOATS = T_DIM * XSTR + 2 * WFRAG_CHUNK + T_DIM;
constexpr int SMEM_BYTES  = SMEM_FLOATS * 4;   // 205,824 B

__device__ __forceinline__ void cp16(void* s, const void* g) {
    uint32_t sa = (uint32_t)__cvta_generic_to_shared(s);
    asm volatile("cp.async.cg.shared.global [%0], [%1], 16;" :: "r"(sa), "l"(g));
}
__device__ __forceinline__ uint32_t f2tf(float f) {
    uint32_t r;
    asm("cvt.rna.tf32.f32 %0, %1;" : "=r"(r) : "f"(f));
    return r;
}
__device__ __forceinline__ void mma_tf32(float* d, const uint32_t* a, const uint32_t* b) {
    asm volatile(
        "mma.sync.aligned.m16n8k8.row.col.f32.tf32.tf32.f32 "
        "{%0,%1,%2,%3}, {%4,%5,%6,%7}, {%8,%9}, {%0,%1,%2,%3};"
        : "+f"(d[0]), "+f"(d[1]), "+f"(d[2]), "+f"(d[3])
        : "r"(a[0]), "r"(a[1]), "r"(a[2]), "r"(a[3]), "r"(b[0]), "r"(b[1]));
}

// Prologue: repack W into per-lane MMA A-fragments, TF32-rounded (rna).
// float4 idx = kc*2048 + ks*512 + wm*64 + mt*32 + lane.
// Fragment (lane: gid=lane>>2, tig=lane&3), r = wm*32 + mt*16 + gid,
// c = kc*32 + ks*8 + tig: { W[r][c], W[r+8][c], W[r][c+4], W[r+8][c+4] }.
__global__ void repack_W_kernel(const float* __restrict__ W)
{
    const int idx  = blockIdx.x * 256 + threadIdx.x;   // float4 index, 0..16383
    const int lane = idx & 31;
    const int mt   = (idx >> 5) & 1;
    const int wm   = (idx >> 6) & 7;
    const int ks   = (idx >> 9) & 3;
    const int kc   = idx >> 11;
    const int gid  = lane >> 2, tig = lane & 3;
    const int r = wm * 32 + mt * 16 + gid;
    const int c = kc * 32 + ks * 8 + tig;
    uint4 u;
    u.x = f2tf(W[(size_t)r * T_DIM + c]);
    u.y = f2tf(W[(size_t)(r + 8) * T_DIM + c]);
    u.z = f2tf(W[(size_t)r * T_DIM + c + 4]);
    u.w = f2tf(W[(size_t)(r + 8) * T_DIM + c + 4]);
    reinterpret_cast<uint4*>(Wpk_g)[idx] = u;
}

__global__ void __launch_bounds__(NTHREADS, 1)
tokengsm_kernel(const float* __restrict__ x, const float* __restrict__ bias,
                float* __restrict__ out)
{
    extern __shared__ float smem[];
    float* Xs = smem;                        // [256][136]
    float* Wb = smem + T_DIM * XSTR;         // [2][8192] fragment-packed
    float* bs = Wb + 2 * WFRAG_CHUNK;        // [256]

    const int tid   = threadIdx.x;
    const int ct    = blockIdx.x;
    const int batch = ct >> 11;                    // 2048 column tiles per batch
    const int j0    = (ct & 2047) * CTILE;
    const float* xb = x   + (size_t)batch * T_DIM * NCOLS;
    float*       ob = out + (size_t)batch * T_DIM * NCOLS;

    if (tid < 256) bs[tid] = bias[tid];

    // ---- stage the FULL X tile (all K rows; also reused by the epilogue) ----
    #pragma unroll
    for (int i = 0; i < 16; ++i) {
        int idx = tid + i * NTHREADS;      // 8192 x 16B segs
        int r = idx >> 5, seg = idx & 31;
        cp16(Xs + r * XSTR + seg * 4, xb + (size_t)r * NCOLS + j0 + seg * 4);
    }
    // ---- W chunk staging (linear copy of pre-packed fragments) ----
    auto submit_w = [&](int kc) {
        const int buf = kc & 1;
        #pragma unroll
        for (int i = 0; i < 4; ++i) {      // 2048 x 16B segs
            int idx = tid + i * NTHREADS;
            cp16(Wb + buf * WFRAG_CHUNK + idx * 4, Wpk_g + kc * WFRAG_CHUNK + idx * 4);
        }
    };
    submit_w(0);
    asm volatile("cp.async.commit_group;" ::: "memory");   // group: X + W0
    submit_w(1);
    asm volatile("cp.async.commit_group;" ::: "memory");   // group: W1

    const int wid  = tid >> 5, lane = tid & 31;
    const int wm   = wid >> 1;            // 0..7 : M block of 32 rows
    const int wn   = wid & 1;             // 0..1 : N block of 64 cols
    const int gid  = lane >> 2;           // 0..7
    const int tig  = lane & 3;            // 0..3

    float d[2][8][4];
    #pragma unroll
    for (int mt = 0; mt < 2; ++mt)
        #pragma unroll
        for (int nt = 0; nt < 8; ++nt)
            #pragma unroll
            for (int r = 0; r < 4; ++r) d[mt][nt][r] = 0.f;

    for (int kc = 0; kc < NKC; ++kc) {
        if (kc < NKC - 1) asm volatile("cp.async.wait_group 1;" ::: "memory");
        else              asm volatile("cp.async.wait_group 0;" ::: "memory");
        __syncthreads();

        const float* Wc = Wb + (kc & 1) * WFRAG_CHUNK + wm * 256 + lane * 4;
        #pragma unroll
        for (int ks = 0; ks < 4; ++ks) {
            const int kk = kc * 32 + ks * 8;
            // A fragments: one LDS.128 per m-tile (pre-rounded tf32 bits)
            uint32_t a[2][4];
            #pragma unroll
            for (int mt = 0; mt < 2; ++mt) {
                uint4 v = *reinterpret_cast<const uint4*>(Wc + ks * 2048 + mt * 128);
                a[mt][0] = v.x; a[mt][1] = v.y; a[mt][2] = v.z; a[mt][3] = v.w;
            }
            // B fragments: raw fp32 bits (HW truncates to tf32)
            uint32_t b[8][2];
            const uint32_t* xr0 = reinterpret_cast<const uint32_t*>(
                Xs + (size_t)(kk + tig) * XSTR + wn * 64 + gid);
            const uint32_t* xr1 = xr0 + 4 * XSTR;
            #pragma unroll
            for (int nt = 0; nt < 8; ++nt) {
                b[nt][0] = xr0[nt * 8];
                b[nt][1] = xr1[nt * 8];
            }
            #pragma unroll
            for (int mt = 0; mt < 2; ++mt)
                #pragma unroll
                for (int nt = 0; nt < 8; ++nt)
                    mma_tf32(d[mt][nt], a[mt], b[nt]);
        }
        __syncthreads();
        if (kc + 2 < NKC) {
            submit_w(kc + 2);
            asm volatile("cp.async.commit_group;" ::: "memory");
        }
    }

    // ---- fused epilogue: gate + channel-sliced temporal shift ----
    // c = (j0+col) & 255 ; c<64: shifted = x[t-1] ; 64<=c<128: x[t+1] ; else x[t]
    #pragma unroll
    for (int mt = 0; mt < 2; ++mt) {
        const int s0 = wm * 32 + mt * 16 + gid;
        #pragma unroll
        for (int nt = 0; nt < 8; ++nt) {
            const int col = wn * 64 + nt * 8 + tig * 2;
            const int cc  = ((j0 + col) >> 6) & 3;   // uniform within 8-col ntile
            #pragma unroll
            for (int h = 0; h < 2; ++h) {
                const int s = s0 + h * 8;
                const float bb = bs[s];
                const float z0 = d[mt][nt][h * 2 + 0] + bb;
                const float z1 = d[mt][nt][h * 2 + 1] + bb;
                const float g0 = __fdividef(1.f, 1.f + __expf(-z0));
                const float g1 = __fdividef(1.f, 1.f + __expf(-z1));
                const float2 xc = *(const float2*)(Xs + (size_t)s * XSTR + col);
                float2 xs;
                if (cc == 0) {
                    xs = (s == 0) ? make_float2(0.f, 0.f)
                                  : *(const float2*)(Xs + (size_t)(s - 1) * XSTR + col);
                } else if (cc == 1) {
                    xs = (s == T_DIM - 1) ? make_float2(0.f, 0.f)
                                          : *(const float2*)(Xs + (size_t)(s + 1) * XSTR + col);
                } else {
                    xs = xc;
                }
                float2 ov;
                ov.x = fmaf(g0, xs.x - xc.x, xc.x);
                ov.y = fmaf(g1, xs.y - xc.y, xc.y);
                *(float2*)(ob + (size_t)s * NCOLS + j0 + col) = ov;
            }
        }
    }
}

extern "C" void kernel_launch(void* const* d_in, const int* in_sizes, int n_in,
                              void* d_out, int out_size)
{
    const float* x = (const float*)d_in[0];   // [2,256,1024,256] fp32
    const float* W = (const float*)d_in[1];   // [256,256]
    const float* b = (const float*)d_in[2];   // [256]
    float* out = (float*)d_out;

    repack_W_kernel<<<64, 256>>>(W);

    cudaFuncSetAttribute(tokengsm_kernel,
                         cudaFuncAttributeMaxDynamicSharedMemorySize, SMEM_BYTES);
    const int grid = BATCH * (NCOLS / CTILE);   // 4096 CTAs
    tokengsm_kernel<<<grid, NTHREADS, SMEM_BYTES>>>(x, b, out);
}

// round 16
// speedup vs baseline: 1.0387x; 1.0387x over previous
#include <cuda_runtime.h>
#include <cstdint>

// x [B=2, T=256, N=1024, C=256] fp32.  GEMM per batch: Y[s,j] = sum_t W[s,t] X[t,j],
// fused with sigmoid gate + channel-sliced temporal shift epilogue.
// mma.sync tf32, 256 threads, 64x64 warp tiles, software-pipelined fragments.

constexpr int T_DIM  = 256;     // time = M = K
constexpr int NCOLS  = 262144;  // N*C per batch
constexpr int BATCH  = 2;
constexpr int CTILE  = 128;     // columns per CTA
constexpr int NKC    = 8;       // K chunks of 32
constexpr int XSTR   = 136;     // X smem row stride (floats) -> conflict-free B frags
constexpr int NTHREADS = 256;   // 8 warps: 4 (M) x 2 (N), 64x64 tiles

// Fragment-packed W: [kc(8)][ks(4)][wm(4)][mt(4)][lane(32)] float4 = 65536 floats
__device__ float Wpk_g[T_DIM * T_DIM];

// SMEM (floats): Xs[256][136] + Wfrag[2][8192] + bias[256]
constexpr int WFRAG_CHUNK = 8192;
constexpr int SMEM_FLOATS = T_DIM * XSTR + 2 * WFRAG_CHUNK + T_DIM;
constexpr int SMEM_BYTES  = SMEM_FLOATS * 4;   // 205,824 B

__device__ __forceinline__ void cp16(void* s, const void* g) {
    uint32_t sa = (uint32_t)__cvta_generic_to_shared(s);
    asm volatile("cp.async.cg.shared.global [%0], [%1], 16;" :: "r"(sa), "l"(g));
}
__device__ __forceinline__ uint32_t f2tf(float f) {
    uint32_t r;
    asm("cvt.rna.tf32.f32 %0, %1;" : "=r"(r) : "f"(f));
    return r;
}
__device__ __forceinline__ void mma_tf32(float* d, const uint32_t* a, const uint32_t* b) {
    asm volatile(
        "mma.sync.aligned.m16n8k8.row.col.f32.tf32.tf32.f32 "
        "{%0,%1,%2,%3}, {%4,%5,%6,%7}, {%8,%9}, {%0,%1,%2,%3};"
        : "+f"(d[0]), "+f"(d[1]), "+f"(d[2]), "+f"(d[3])
        : "r"(a[0]), "r"(a[1]), "r"(a[2]), "r"(a[3]), "r"(b[0]), "r"(b[1]));
}

// Repack W into per-lane MMA A-fragments, TF32-rounded (rna).
// float4 idx = kc*2048 + ks*512 + wm*128 + mt*32 + lane.
// Fragment (gid=lane>>2, tig=lane&3), r = wm*64 + mt*16 + gid, c = kc*32 + ks*8 + tig:
//   { W[r][c], W[r+8][c], W[r][c+4], W[r+8][c+4] }.
__global__ void repack_W_kernel(const float* __restrict__ W)
{
    const int idx  = blockIdx.x * 256 + threadIdx.x;   // float4 index, 0..16383
    const int lane = idx & 31;
    const int mt   = (idx >> 5) & 3;
    const int wm   = (idx >> 7) & 3;
    const int ks   = (idx >> 9) & 3;
    const int kc   = idx >> 11;
    const int gid  = lane >> 2, tig = lane & 3;
    const int r = wm * 64 + mt * 16 + gid;
    const int c = kc * 32 + ks * 8 + tig;
    uint4 u;
    u.x = f2tf(W[(size_t)r * T_DIM + c]);
    u.y = f2tf(W[(size_t)(r + 8) * T_DIM + c]);
    u.z = f2tf(W[(size_t)r * T_DIM + c + 4]);
    u.w = f2tf(W[(size_t)(r + 8) * T_DIM + c + 4]);
    reinterpret_cast<uint4*>(Wpk_g)[idx] = u;
}

__global__ void __launch_bounds__(NTHREADS, 1)
tokengsm_kernel(const float* __restrict__ x, const float* __restrict__ bias,
                float* __restrict__ out)
{
    extern __shared__ float smem[];
    float* Xs = smem;                        // [256][136]
    float* Wb = smem + T_DIM * XSTR;         // [2][8192] fragment-packed
    float* bs = Wb + 2 * WFRAG_CHUNK;        // [256]

    const int tid   = threadIdx.x;
    const int ct    = blockIdx.x;
    const int batch = ct >> 11;
    const int j0    = (ct & 2047) * CTILE;
    const float* xb = x   + (size_t)batch * T_DIM * NCOLS;
    float*       ob = out + (size_t)batch * T_DIM * NCOLS;

    bs[tid] = bias[tid];

    // ---- stage FULL X tile up front (also reused by the epilogue) ----
    #pragma unroll
    for (int i = 0; i < 32; ++i) {
        int idx = tid + i * NTHREADS;      // 8192 x 16B segs
        int r = idx >> 5, seg = idx & 31;
        cp16(Xs + r * XSTR + seg * 4, xb + (size_t)r * NCOLS + j0 + seg * 4);
    }
    auto submit_w = [&](int kc) {
        const int buf = kc & 1;
        #pragma unroll
        for (int i = 0; i < 8; ++i) {      // 2048 x 16B segs
            int idx = tid + i * NTHREADS;
            cp16(Wb + buf * WFRAG_CHUNK + idx * 4, Wpk_g + kc * WFRAG_CHUNK + idx * 4);
        }
    };
    submit_w(0);
    asm volatile("cp.async.commit_group;" ::: "memory");   // group: X + W0
    submit_w(1);
    asm volatile("cp.async.commit_group;" ::: "memory");   // group: W1

    const int wid  = tid >> 5, lane = tid & 31;
    const int wm   = wid >> 1;            // 0..3 : M block of 64 rows
    const int wn   = wid & 1;             // 0..1 : N block of 64 cols
    const int gid  = lane >> 2;
    const int tig  = lane & 3;

    float d[4][8][4];
    #pragma unroll
    for (int mt = 0; mt < 4; ++mt)
        #pragma unroll
        for (int nt = 0; nt < 8; ++nt)
            #pragma unroll
            for (int r = 0; r < 4; ++r) d[mt][nt][r] = 0.f;

    // Double-buffered fragments for software pipelining
    uint32_t a[2][4][4], b[2][8][2];

    const uint32_t* Xu = reinterpret_cast<const uint32_t*>(Xs);

    for (int kc = 0; kc < NKC; ++kc) {
        if (kc < NKC - 1) asm volatile("cp.async.wait_group 1;" ::: "memory");
        else              asm volatile("cp.async.wait_group 0;" ::: "memory");
        __syncthreads();

        const float* Wc = Wb + (kc & 1) * WFRAG_CHUNK + wm * 512 + lane * 4;

        // prologue: load fragments for ks=0
        {
            #pragma unroll
            for (int mt = 0; mt < 4; ++mt) {
                uint4 v = *reinterpret_cast<const uint4*>(Wc + mt * 128);
                a[0][mt][0] = v.x; a[0][mt][1] = v.y;
                a[0][mt][2] = v.z; a[0][mt][3] = v.w;
            }
            const uint32_t* xr0 = Xu + (size_t)(kc * 32 + tig) * XSTR + wn * 64 + gid;
            const uint32_t* xr1 = xr0 + 4 * XSTR;
            #pragma unroll
            for (int nt = 0; nt < 8; ++nt) {
                b[0][nt][0] = xr0[nt * 8];
                b[0][nt][1] = xr1[nt * 8];
            }
        }

        #pragma unroll
        for (int ks = 0; ks < 4; ++ks) {
            const int cur = ks & 1, nxt = cur ^ 1;
            // prefetch ks+1 fragments before issuing ks MMAs
            if (ks < 3) {
                #pragma unroll
                for (int mt = 0; mt < 4; ++mt) {
                    uint4 v = *reinterpret_cast<const uint4*>(
                        Wc + (ks + 1) * 2048 + mt * 128);
                    a[nxt][mt][0] = v.x; a[nxt][mt][1] = v.y;
                    a[nxt][mt][2] = v.z; a[nxt][mt][3] = v.w;
                }
                const uint32_t* xr0 = Xu +
                    (size_t)(kc * 32 + (ks + 1) * 8 + tig) * XSTR + wn * 64 + gid;
                const uint32_t* xr1 = xr0 + 4 * XSTR;
                #pragma unroll
                for (int nt = 0; nt < 8; ++nt) {
                    b[nxt][nt][0] = xr0[nt * 8];
                    b[nxt][nt][1] = xr1[nt * 8];
                }
            }
            #pragma unroll
            for (int mt = 0; mt < 4; ++mt)
                #pragma unroll
                for (int nt = 0; nt < 8; ++nt)
                    mma_tf32(d[mt][nt], a[cur][mt], b[cur][nt]);
        }

        __syncthreads();
        if (kc + 2 < NKC) {
            submit_w(kc + 2);
            asm volatile("cp.async.commit_group;" ::: "memory");
        }
    }

    // ---- fused epilogue: gate + channel-sliced temporal shift ----
    // c = (j0+col) & 255 ; c<64: shifted = x[t-1] ; 64<=c<128: x[t+1] ; else x[t]
    #pragma unroll
    for (int mt = 0; mt < 4; ++mt) {
        const int s0 = wm * 64 + mt * 16 + gid;
        #pragma unroll
        for (int nt = 0; nt < 8; ++nt) {
            const int col = wn * 64 + nt * 8 + tig * 2;
            const int cc  = ((j0 + col) >> 6) & 3;   // uniform within 8-col ntile
            #pragma unroll
            for (int h = 0; h < 2; ++h) {
                const int s = s0 + h * 8;
                const float bb = bs[s];
                const float z0 = d[mt][nt][h * 2 + 0] + bb;
                const float z1 = d[mt][nt][h * 2 + 1] + bb;
                const float g0 = __fdividef(1.f, 1.f + __expf(-z0));
                const float g1 = __fdividef(1.f, 1.f + __expf(-z1));
                const float2 xc = *(const float2*)(Xs + (size_t)s * XSTR + col);
                float2 xs;
                if (cc == 0) {
                    xs = (s == 0) ? make_float2(0.f, 0.f)
                                  : *(const float2*)(Xs + (size_t)(s - 1) * XSTR + col);
                } else if (cc == 1) {
                    xs = (s == T_DIM - 1) ? make_float2(0.f, 0.f)
                                          : *(const float2*)(Xs + (size_t)(s + 1) * XSTR + col);
                } else {
                    xs = xc;
                }
                float2 ov;
                ov.x = fmaf(g0, xs.x - xc.x, xc.x);
                ov.y = fmaf(g1, xs.y - xc.y, xc.y);
                *(float2*)(ob + (size_t)s * NCOLS + j0 + col) = ov;
            }
        }
    }
}

extern "C" void kernel_launch(void* const* d_in, const int* in_sizes, int n_in,
                              void* d_out, int out_size)
{
    const float* x = (const float*)d_in[0];   // [2,256,1024,256] fp32
    const float* W = (const float*)d_in[1];   // [256,256]
    const float* b = (const float*)d_in[2];   // [256]
    float* out = (float*)d_out;

    repack_W_kernel<<<64, 256>>>(W);

    cudaFuncSetAttribute(tokengsm_kernel,
                         cudaFuncAttributeMaxDynamicSharedMemorySize, SMEM_BYTES);
    const int grid = BATCH * (NCOLS / CTILE);   // 4096 CTAs
    tokengsm_kernel<<<grid, NTHREADS, SMEM_BYTES>>>(x, b, out);
}

// round 17
// speedup vs baseline: 1.2743x; 1.2268x over previous
#include <cuda_runtime.h>
#include <cuda_fp16.h>
#include <cstdint>

// x [B=2, T=256, N=1024, C=256] fp32.  GEMM per batch: Y[s,j] = sum_t W[s,t] X[t,j],
// fused with sigmoid gate + channel-sliced temporal shift epilogue.
// mma.sync m16n8k16 fp16 (fp32 accum), 256 threads, 64x64 warp tiles.

constexpr int T_DIM  = 256;     // time = M = K
constexpr int NCOLS  = 262144;  // N*C per batch
constexpr int BATCH  = 2;
constexpr int CTILE  = 128;     // columns per CTA
constexpr int NKC    = 8;       // K chunks of 32
constexpr int XSTR   = 132;     // X smem row stride (floats); 132%32=4 -> banks 8t+g
constexpr int NTHREADS = 256;   // 8 warps: 4 (M) x 2 (N), 64x64 tiles

// Fragment-packed W (fp16x2): [kc(8)][ksp(2)][wm(4)][mt(4)][lane(32)][reg(4)] u32
__device__ uint32_t Wpk_g[32768];

// SMEM (floats): Xs[256][132] + Wfrag[2][4096 u32] + bias[256]
constexpr int WFRAG_U32 = 4096;         // u32 per K-chunk of packed W (16 KB)
constexpr int SMEM_FLOATS = T_DIM * XSTR + 2 * WFRAG_U32 + T_DIM;
constexpr int SMEM_BYTES  = SMEM_FLOATS * 4;   // 169,984 B

__device__ __forceinline__ void cp16(void* s, const void* g) {
    uint32_t sa = (uint32_t)__cvta_generic_to_shared(s);
    asm volatile("cp.async.cg.shared.global [%0], [%1], 16;" :: "r"(sa), "l"(g));
}
__device__ __forceinline__ uint32_t packh2(float lo, float hi) {
    __half2 h = __floats2half2_rn(lo, hi);
    return *reinterpret_cast<uint32_t*>(&h);
}
__device__ __forceinline__ void mma_f16(float* d, const uint32_t* a, const uint32_t* b) {
    asm volatile(
        "mma.sync.aligned.m16n8k16.row.col.f32.f16.f16.f32 "
        "{%0,%1,%2,%3}, {%4,%5,%6,%7}, {%8,%9}, {%0,%1,%2,%3};"
        : "+f"(d[0]), "+f"(d[1]), "+f"(d[2]), "+f"(d[3])
        : "r"(a[0]), "r"(a[1]), "r"(a[2]), "r"(a[3]), "r"(b[0]), "r"(b[1]));
}

// Repack W into per-lane m16n8k16 A-fragments (fp16x2, rn).
// u32 idx = kc*4096 + ksp*2048 + wm*512 + mt*128 + lane*4 + reg.
// gid=lane>>2, tig=lane&3;  r = wm*64+mt*16+gid + (reg&1)*8;
// c = kc*32+ksp*16+tig*2 + (reg>>1)*8;  val = pack(W[r][c], W[r][c+1]).
__global__ void repack_W_kernel(const float* __restrict__ W)
{
    const int idx  = blockIdx.x * 256 + threadIdx.x;   // 0..32767
    const int reg  = idx & 3;
    const int lane = (idx >> 2) & 31;
    const int mt   = (idx >> 7) & 3;
    const int wm   = (idx >> 9) & 3;
    const int ksp  = (idx >> 11) & 1;
    const int kc   = idx >> 12;
    const int gid  = lane >> 2, tig = lane & 3;
    const int r = wm * 64 + mt * 16 + gid + (reg & 1) * 8;
    const int c = kc * 32 + ksp * 16 + tig * 2 + (reg >> 1) * 8;
    Wpk_g[idx] = packh2(W[(size_t)r * T_DIM + c], W[(size_t)r * T_DIM + c + 1]);
}

__global__ void __launch_bounds__(NTHREADS, 1)
tokengsm_kernel(const float* __restrict__ x, const float* __restrict__ bias,
                float* __restrict__ out)
{
    extern __shared__ float smem[];
    float*    Xs = smem;                                  // [256][132]
    uint32_t* Wb = (uint32_t*)(smem + T_DIM * XSTR);      // [2][4096]
    float*    bs = smem + T_DIM * XSTR + 2 * WFRAG_U32;   // [256]

    const int tid   = threadIdx.x;
    const int ct    = blockIdx.x;
    const int batch = ct >> 11;
    const int j0    = (ct & 2047) * CTILE;
    const float* xb = x   + (size_t)batch * T_DIM * NCOLS;
    float*       ob = out + (size_t)batch * T_DIM * NCOLS;

    bs[tid] = bias[tid];

    // ---- stage FULL X tile up front (mainloop B source + epilogue) ----
    #pragma unroll
    for (int i = 0; i < 32; ++i) {
        int idx = tid + i * NTHREADS;      // 8192 x 16B segs
        int r = idx >> 5, seg = idx & 31;
        cp16(Xs + r * XSTR + seg * 4, xb + (size_t)r * NCOLS + j0 + seg * 4);
    }
    auto submit_w = [&](int kc) {
        const int buf = kc & 1;
        #pragma unroll
        for (int i = 0; i < 4; ++i) {      // 1024 x 16B segs
            int idx = tid + i * NTHREADS;
            cp16(Wb + buf * WFRAG_U32 + idx * 4, Wpk_g + kc * WFRAG_U32 + idx * 4);
        }
    };
    submit_w(0);
    asm volatile("cp.async.commit_group;" ::: "memory");   // group: X + W0
    submit_w(1);
    asm volatile("cp.async.commit_group;" ::: "memory");   // group: W1

    const int wid  = tid >> 5, lane = tid & 31;
    const int wm   = wid >> 1;            // 0..3 : M block of 64 rows
    const int wn   = wid & 1;             // 0..1 : N block of 64 cols
    const int gid  = lane >> 2;           // 0..7
    const int tig  = lane & 3;            // 0..3

    float d[4][8][4];
    #pragma unroll
    for (int mt = 0; mt < 4; ++mt)
        #pragma unroll
        for (int nt = 0; nt < 8; ++nt)
            #pragma unroll
            for (int r = 0; r < 4; ++r) d[mt][nt][r] = 0.f;

    for (int kc = 0; kc < NKC; ++kc) {
        if (kc < NKC - 1) asm volatile("cp.async.wait_group 1;" ::: "memory");
        else              asm volatile("cp.async.wait_group 0;" ::: "memory");
        __syncthreads();

        const uint32_t* Wc = Wb + (kc & 1) * WFRAG_U32 + wm * 512 + lane * 4;
        #pragma unroll
        for (int ks = 0; ks < 2; ++ks) {          // two k16 steps per chunk
            const int kk = kc * 32 + ks * 16;
            // A fragments: one LDS.128 per m-tile (pre-packed fp16x2)
            uint32_t a[4][4];
            #pragma unroll
            for (int mt = 0; mt < 4; ++mt) {
                uint4 v = *reinterpret_cast<const uint4*>(Wc + ks * 2048 + mt * 128);
                a[mt][0] = v.x; a[mt][1] = v.y; a[mt][2] = v.z; a[mt][3] = v.w;
            }
            // B fragments: pack fp32 row pairs -> fp16x2 on the fly
            // reg0: k = kk+2*tig, kk+2*tig+1 ; reg1: +8
            uint32_t b[8][2];
            const float* xp = Xs + (size_t)(kk + 2 * tig) * XSTR + wn * 64 + gid;
            #pragma unroll
            for (int nt = 0; nt < 8; ++nt) {
                const float* p = xp + nt * 8;
                b[nt][0] = packh2(p[0],        p[XSTR]);
                b[nt][1] = packh2(p[8 * XSTR], p[9 * XSTR]);
            }
            #pragma unroll
            for (int mt = 0; mt < 4; ++mt)
                #pragma unroll
                for (int nt = 0; nt < 8; ++nt)
                    mma_f16(d[mt][nt], a[mt], b[nt]);
        }
        __syncthreads();
        if (kc + 2 < NKC) {
            submit_w(kc + 2);
            asm volatile("cp.async.commit_group;" ::: "memory");
        }
    }

    // ---- fused epilogue: gate + channel-sliced temporal shift ----
    // c = (j0+col) & 255 ; c<64: shifted = x[t-1] ; 64<=c<128: x[t+1] ; else x[t]
    #pragma unroll
    for (int mt = 0; mt < 4; ++mt) {
        const int s0 = wm * 64 + mt * 16 + gid;
        #pragma unroll
        for (int nt = 0; nt < 8; ++nt) {
            const int col = wn * 64 + nt * 8 + tig * 2;
            const int cc  = ((j0 + col) >> 6) & 3;   // uniform within 8-col ntile
            #pragma unroll
            for (int h = 0; h < 2; ++h) {
                const int s = s0 + h * 8;
                const float bb = bs[s];
                const float z0 = d[mt][nt][h * 2 + 0] + bb;
                const float z1 = d[mt][nt][h * 2 + 1] + bb;
                const float g0 = __fdividef(1.f, 1.f + __expf(-z0));
                const float g1 = __fdividef(1.f, 1.f + __expf(-z1));
                const float2 xc = *(const float2*)(Xs + (size_t)s * XSTR + col);
                float2 xs;
                if (cc == 0) {
                    xs = (s == 0) ? make_float2(0.f, 0.f)
                                  : *(const float2*)(Xs + (size_t)(s - 1) * XSTR + col);
                } else if (cc == 1) {
                    xs = (s == T_DIM - 1) ? make_float2(0.f, 0.f)
                                          : *(const float2*)(Xs + (size_t)(s + 1) * XSTR + col);
                } else {
                    xs = xc;
                }
                float2 ov;
                ov.x = fmaf(g0, xs.x - xc.x, xc.x);
                ov.y = fmaf(g1, xs.y - xc.y, xc.y);
                *(float2*)(ob + (size_t)s * NCOLS + j0 + col) = ov;
            }
        }
    }
}

extern "C" void kernel_launch(void* const* d_in, const int* in_sizes, int n_in,
                              void* d_out, int out_size)
{
    const float* x = (const float*)d_in[0];   // [2,256,1024,256] fp32
    const float* W = (const float*)d_in[1];   // [256,256]
    const float* b = (const float*)d_in[2];   // [256]
    float* out = (float*)d_out;

    repack_W_kernel<<<128, 256>>>(W);

    cudaFuncSetAttribute(tokengsm_kernel,
                         cudaFuncAttributeMaxDynamicSharedMemorySize, SMEM_BYTES);
    const int grid = BATCH * (NCOLS / CTILE);   // 4096 CTAs
    tokengsm_kernel<<<grid, NTHREADS, SMEM_BYTES>>>(x, b, out);
}